// round 6
// baseline (speedup 1.0000x reference)
#include <cuda_runtime.h>
#include <cuda_fp16.h>
#include <cstdint>
#include <cstddef>

#define D   64
#define H   4
#define NEG 0.2f
#define BN_EPS 1e-5f

#define NMAX 50000
#define EMAX 800000

// ---------------- scratch (static device globals; no allocation) ----------------
__device__ __half2 g_hh[(size_t)NMAX * 128];    // [N][pair p][head h] fp16 features
__device__ float  g_asrc[NMAX * H];
__device__ float  g_adst[NMAX * H];
__device__ float  g_wcsr[(size_t)EMAX * H];     // per-edge weights (CSR order)
__device__ float  g_wself[NMAX * H];
__device__ float  g_dnm[NMAX * H];              // softmax denominators (atomic)
__device__ float  g_cs[H * D];                  // W_gat_h^T att_src_h
__device__ float  g_cd[H * D];                  // W_gat_h^T att_dst_h
__device__ int    g_cnt[NMAX];
__device__ int    g_rowptr[NMAX + 1];
__device__ int    g_cursor[NMAX];
__device__ int    g_csrc[EMAX];
__device__ int    g_bsum[256];
__device__ double g_sums[128];                  // [0:64) sum, [64:128) sumsq
__device__ float  g_bnsc[64], g_bnsh[64];

// ---------------- fast exp: FMA polynomial (no MUFU) ----------------
__device__ __forceinline__ float fexp(float x) {
    x = fmaxf(x, -80.f);
    float y  = x * 1.44269504089f;
    float t  = y + 12582912.0f;
    int   ki = __float_as_int(t) - 0x4B400000;
    float r  = y - (t - 12582912.0f);
    float p  = 1.5403530e-4f;
    p = fmaf(p, r, 1.3333558e-3f);
    p = fmaf(p, r, 9.6181291e-3f);
    p = fmaf(p, r, 5.5504109e-2f);
    p = fmaf(p, r, 2.4022651e-1f);
    p = fmaf(p, r, 6.9314718e-1f);
    p = fmaf(p, r, 1.0f);
    return __int_as_float(__float_as_int(p) + (ki << 23));
}

__device__ __forceinline__ float lrelu(float v) { return (v >= 0.f) ? v : NEG * v; }

// ============================================================================
// prep kernels (3 tiny launches so launch #4 = k_linear2 gets profiled)
// ============================================================================
__global__ void k_prep_vec(const float* __restrict__ Wgat,
                           const float* __restrict__ attS,
                           const float* __restrict__ attD) {
    int tid = threadIdx.x;              // 256
    int h = tid >> 6, k = tid & 63;
    float s = 0.f, d2 = 0.f;
    #pragma unroll 8
    for (int dd = 0; dd < 64; dd++) {
        float wv = Wgat[(h * 64 + dd) * 64 + k];
        s  += attS[h * 64 + dd] * wv;
        d2 += attD[h * 64 + dd] * wv;
    }
    g_cs[tid] = s;
    g_cd[tid] = d2;
}

__global__ void k_zero(int n) {
    int gid = blockIdx.x * blockDim.x + threadIdx.x;
    int stride = gridDim.x * blockDim.x;
    for (int i = gid; i < n; i += stride) g_cnt[i] = 0;
    for (int i = gid; i < n * 4; i += stride) g_dnm[i] = 0.f;
}

__global__ void k_zero_sums() {
    if (threadIdx.x < 128) g_sums[threadIdx.x] = 0.0;
}

// ============================================================================
// K1: fused  u = PReLU(x W_lin^T + b);  h = u W_gat^T (fp16, head-interleaved,
//     two 128-col passes to keep smem at ~74KB -> 2-3 CTAs/SM);
//     a_src/a_dst dots;  + destination histogram (overlapped)
// ============================================================================
// smem floats: sX 64*72 + sU 64*72 + sW 64*136 + 2*4*68
#define K1_SMEM ((64*72 + 64*72 + 64*136 + 2*4*68) * 4)

__global__ __launch_bounds__(256, 2) void k_linear2(
    const float* __restrict__ x, const float* __restrict__ Wlin,
    const float* __restrict__ blin, const float* __restrict__ pw,
    const float* __restrict__ Wgat, const int* __restrict__ dstA,
    int nrows, int nedges)
{
    extern __shared__ float sm[];
    float* sX  = sm;                         // [64][72]
    float* sU  = sm + 64 * 72;               // [64][72]
    float* sW  = sm + 2 * 64 * 72;           // [64][136]  (128 cols per pass)
    float* sC  = sm + 2 * 64 * 72 + 64 * 136;    // [4][68]
    float* sC2 = sC + 4 * 68;                    // [4][68]
    const int tid  = threadIdx.x;
    const int row0 = blockIdx.x * 64;

    // destination histogram (independent, overlaps FFMA work)
    {
        int gid = blockIdx.x * 256 + tid;
        int stride = gridDim.x * 256;
        for (int i = gid; i < nedges; i += stride)
            atomicAdd(&g_cnt[dstA[i]], 1);
    }

    {
        int h = tid >> 6, k = tid & 63;
        sC [h * 68 + k] = g_cs[tid];
        sC2[h * 68 + k] = g_cd[tid];
    }
    for (int i = tid; i < 64 * 64; i += 256) {
        int r = i >> 6, k = i & 63;
        int gr = row0 + r;
        sX[k * 72 + r] = (gr < nrows) ? x[(size_t)gr * D + k] : 0.f;
    }
    // W_lin into sW (fits: 64x64 <= 64x136 region)
    for (int i = tid; i < 64 * 64; i += 256) {
        int j = i >> 6, k = i & 63;
        sW[k * 136 + j] = Wlin[i];
    }
    __syncthreads();

    // ---- stage A: u = PReLU(x W_lin^T + b) -> sU (transposed) ----
    {
        const int rg = (tid >> 4) << 2;
        const int cg = (tid & 15) << 2;
        float acc[4][4];
        #pragma unroll
        for (int a = 0; a < 4; a++)
            #pragma unroll
            for (int b = 0; b < 4; b++) acc[a][b] = 0.f;
        #pragma unroll 8
        for (int k = 0; k < 64; k++) {
            float4 a4 = *(const float4*)(sX + k * 72 + rg);
            float4 b4 = *(const float4*)(sW + k * 136 + cg);
            float av[4] = {a4.x, a4.y, a4.z, a4.w};
            float bv[4] = {b4.x, b4.y, b4.z, b4.w};
            #pragma unroll
            for (int ri = 0; ri < 4; ri++)
                #pragma unroll
                for (int cj = 0; cj < 4; cj++) acc[ri][cj] += av[ri] * bv[cj];
        }
        float4 bb = *(const float4*)(blin + cg);
        float4 pp = *(const float4*)(pw + cg);
        float bvb[4] = {bb.x, bb.y, bb.z, bb.w};
        float pvb[4] = {pp.x, pp.y, pp.z, pp.w};
        #pragma unroll
        for (int ri = 0; ri < 4; ri++)
            #pragma unroll
            for (int cj = 0; cj < 4; cj++) {
                float v = acc[ri][cj] + bvb[cj];
                v = (v >= 0.f) ? v : pvb[cj] * v;
                sU[(cg + cj) * 72 + rg + ri] = v;
            }
    }

    // ---- stage B: h = u W_gat^T in two 128-col passes (8x4 micro-tiles) ----
    const int lane = tid & 31;
    const int r0   = (tid >> 5) << 3;     // 8-row group
    const int mlo  = lane << 2;           // 4 cols within the 128-col pass

    #pragma unroll
    for (int half = 0; half < 2; half++) {
        __syncthreads();    // sW readers of previous pass done / sU written
        for (int i = tid; i < 128 * 64; i += 256) {
            int m = i >> 6, k = i & 63;
            sW[k * 136 + m] = Wgat[(half * 128 + m) * 64 + k];
        }
        __syncthreads();

        float acc[8][4];
        #pragma unroll
        for (int a = 0; a < 8; a++)
            #pragma unroll
            for (int b = 0; b < 4; b++) acc[a][b] = 0.f;

        #pragma unroll 8
        for (int k = 0; k < 64; k++) {
            float4 a0 = *(const float4*)(sU + k * 72 + r0);
            float4 a1 = *(const float4*)(sU + k * 72 + r0 + 4);
            float4 b0 = *(const float4*)(sW + k * 136 + mlo);
            float av[8] = {a0.x, a0.y, a0.z, a0.w, a1.x, a1.y, a1.z, a1.w};
            float bv[4] = {b0.x, b0.y, b0.z, b0.w};
            #pragma unroll
            for (int ri = 0; ri < 8; ri++)
                #pragma unroll
                for (int cj = 0; cj < 4; cj++) acc[ri][cj] += av[ri] * bv[cj];
        }

        // fp16 head-interleaved store: g_hh[gr*128 + p*4 + h]
        const int hh = half * 2 + (mlo >> 6);   // head index
        const int p0 = (mlo & 63) >> 1;         // even pair index
        #pragma unroll
        for (int ri = 0; ri < 8; ri++) {
            int gr = row0 + r0 + ri;
            if (gr < nrows) {
                __half2* hp = g_hh + (size_t)gr * 128;
                hp[p0 * 4 + hh]       = __floats2half2_rn(acc[ri][0], acc[ri][1]);
                hp[(p0 + 1) * 4 + hh] = __floats2half2_rn(acc[ri][2], acc[ri][3]);
            }
        }
    }

    // attention dots from sU (sU untouched by stage B)
    {
        const int r = tid >> 2, h = tid & 3;
        float sa = 0.f, da = 0.f;
        #pragma unroll 8
        for (int k = 0; k < 64; k++) {
            float uv = sU[k * 72 + r];
            sa += uv * sC [h * 68 + k];
            da += uv * sC2[h * 68 + k];
        }
        int gr = row0 + r;
        if (gr < nrows) {
            g_asrc[gr * 4 + h] = sa;
            g_adst[gr * 4 + h] = da;
        }
    }
}

// ============================================================================
// scan
// ============================================================================
__global__ void k_scanA(int n) {
    __shared__ int sh[512];
    int i = blockIdx.x * 512 + threadIdx.x;
    int v = (i < n) ? g_cnt[i] : 0;
    sh[threadIdx.x] = v;
    __syncthreads();
    #pragma unroll
    for (int off = 1; off < 512; off <<= 1) {
        int t = (threadIdx.x >= off) ? sh[threadIdx.x - off] : 0;
        __syncthreads();
        sh[threadIdx.x] += t;
        __syncthreads();
    }
    if (i < n) g_rowptr[i] = sh[threadIdx.x] - v;
    if (threadIdx.x == 511) g_bsum[blockIdx.x] = sh[511];
}

__global__ void k_scanB(int nch) {
    __shared__ int sh[256];
    int v = (threadIdx.x < nch) ? g_bsum[threadIdx.x] : 0;
    sh[threadIdx.x] = v;
    __syncthreads();
    #pragma unroll
    for (int off = 1; off < 256; off <<= 1) {
        int t = (threadIdx.x >= off) ? sh[threadIdx.x - off] : 0;
        __syncthreads();
        sh[threadIdx.x] += t;
        __syncthreads();
    }
    if (threadIdx.x < nch) g_bsum[threadIdx.x] = sh[threadIdx.x] - v;
}

__global__ void k_scanC(int n, int e) {
    int i = blockIdx.x * blockDim.x + threadIdx.x;
    if (i < n) {
        int v = g_rowptr[i] + g_bsum[i >> 9];
        g_rowptr[i] = v;
        g_cursor[i] = v;
    }
    if (i == 0) g_rowptr[n] = e;
}

// ============================================================================
// K2: fused edge weights + CSR scatter (no max pass; magnitudes bounded).
// ============================================================================
__global__ __launch_bounds__(256) void k_edgeW(const int* __restrict__ src,
                                               const int* __restrict__ dst,
                                               int n, int e)
{
    int i = blockIdx.x * 256 + threadIdx.x;
    if (i < e) {
        int s = src[i], d = dst[i];
        float4 a = ((const float4*)g_asrc)[s];
        float4 b = ((const float4*)g_adst)[d];
        float4 w = make_float4(fexp(lrelu(a.x + b.x)), fexp(lrelu(a.y + b.y)),
                               fexp(lrelu(a.z + b.z)), fexp(lrelu(a.w + b.w)));
        int pos = atomicAdd(&g_cursor[d], 1);
        g_csrc[pos] = s;
        ((float4*)g_wcsr)[pos] = w;
        float* dn = g_dnm + d * 4;
        atomicAdd(dn + 0, w.x);
        atomicAdd(dn + 1, w.y);
        atomicAdd(dn + 2, w.z);
        atomicAdd(dn + 3, w.w);
    } else if (i < e + n) {
        int v = i - e;
        float4 a = ((const float4*)g_asrc)[v];
        float4 b = ((const float4*)g_adst)[v];
        float4 w = make_float4(fexp(lrelu(a.x + b.x)), fexp(lrelu(a.y + b.y)),
                               fexp(lrelu(a.z + b.z)), fexp(lrelu(a.w + b.w)));
        ((float4*)g_wself)[v] = w;
        float* dn = g_dnm + v * 4;
        atomicAdd(dn + 0, w.x);
        atomicAdd(dn + 1, w.y);
        atomicAdd(dn + 2, w.z);
        atomicAdd(dn + 3, w.w);
    }
}

// ============================================================================
// K4: warp-per-node weighted gather (one LDG.128 per lane per source row)
// ============================================================================
__global__ __launch_bounds__(256) void k_gather(float* __restrict__ out, int n)
{
    int gw = (blockIdx.x * blockDim.x + threadIdx.x) >> 5;
    if (gw >= n) return;
    const int lane = threadIdx.x & 31;

    float4 ws = ((const float4*)g_wself)[gw];
    uint4 hv = ((const uint4*)(g_hh + (size_t)gw * 128))[lane];
    float2 f0 = __half22float2(*(__half2*)&hv.x);
    float2 f1 = __half22float2(*(__half2*)&hv.y);
    float2 f2 = __half22float2(*(__half2*)&hv.z);
    float2 f3 = __half22float2(*(__half2*)&hv.w);
    float2 A0 = make_float2(ws.x * f0.x, ws.x * f0.y);
    float2 A1 = make_float2(ws.y * f1.x, ws.y * f1.y);
    float2 A2 = make_float2(ws.z * f2.x, ws.z * f2.y);
    float2 A3 = make_float2(ws.w * f3.x, ws.w * f3.y);

    const int eb = g_rowptr[gw], ee = g_rowptr[gw + 1];
    #pragma unroll 2
    for (int e = eb; e < ee; e++) {
        int src  = g_csrc[e];
        float4 w = ((const float4*)g_wcsr)[e];
        uint4 sv = ((const uint4*)(g_hh + (size_t)src * 128))[lane];
        float2 b0 = __half22float2(*(__half2*)&sv.x);
        float2 b1 = __half22float2(*(__half2*)&sv.y);
        float2 b2 = __half22float2(*(__half2*)&sv.z);
        float2 b3 = __half22float2(*(__half2*)&sv.w);
        A0.x = fmaf(w.x, b0.x, A0.x); A0.y = fmaf(w.x, b0.y, A0.y);
        A1.x = fmaf(w.y, b1.x, A1.x); A1.y = fmaf(w.y, b1.y, A1.y);
        A2.x = fmaf(w.z, b2.x, A2.x); A2.y = fmaf(w.z, b2.y, A2.y);
        A3.x = fmaf(w.w, b3.x, A3.x); A3.y = fmaf(w.w, b3.y, A3.y);
    }

    float4 dn = ((const float4*)g_dnm)[gw];
    float i0 = 0.25f / dn.x, i1 = 0.25f / dn.y, i2 = 0.25f / dn.z, i3 = 0.25f / dn.w;
    float2 o;
    o.x = A0.x * i0 + A1.x * i1 + A2.x * i2 + A3.x * i3;
    o.y = A0.y * i0 + A1.y * i1 + A2.y * i2 + A3.y * i3;
    ((float2*)out)[(size_t)gw * 32 + lane] = o;
}

// ============================================================================
// BatchNorm (batch stats; gat_bias cancels) + ReLU
// ============================================================================
__global__ void k_bnstats(const float* __restrict__ out, int nnodes) {
    __shared__ double shs[256], shq[256];
    const int c = threadIdx.x & 63;
    const int g = threadIdx.x >> 6;
    double s = 0.0, q = 0.0;
    for (int r = blockIdx.x * 4 + g; r < nnodes; r += gridDim.x * 4) {
        float v = out[(size_t)r * D + c];
        s += v;
        q += (double)v * v;
    }
    shs[threadIdx.x] = s; shq[threadIdx.x] = q;
    __syncthreads();
    if (g == 0) {
        s = shs[c] + shs[c + 64] + shs[c + 128] + shs[c + 192];
        q = shq[c] + shq[c + 64] + shq[c + 128] + shq[c + 192];
        atomicAdd(&g_sums[c], s);
        atomicAdd(&g_sums[64 + c], q);
    }
}

__global__ void k_bnprep(const float* __restrict__ gamma,
                         const float* __restrict__ beta, int nnodes) {
    int c = threadIdx.x;
    if (c < 64) {
        double mean = g_sums[c] / nnodes;
        double var  = g_sums[64 + c] / nnodes - mean * mean;
        float scale = gamma[c] * rsqrtf((float)var + BN_EPS);
        g_bnsc[c] = scale;
        g_bnsh[c] = beta[c] - (float)mean * scale;
    }
}

__global__ void k_bnfinal(float* __restrict__ out, int nnodes) {
    int i = blockIdx.x * blockDim.x + threadIdx.x;
    int total = nnodes * 16;
    if (i >= total) return;
    int c4 = (i & 15) << 2;
    float4 v = ((float4*)out)[i];
    float4 sc = *(const float4*)(g_bnsc + c4);
    float4 sh = *(const float4*)(g_bnsh + c4);
    v.x = fmaxf(0.f, v.x * sc.x + sh.x);
    v.y = fmaxf(0.f, v.y * sc.y + sh.y);
    v.z = fmaxf(0.f, v.z * sc.z + sh.z);
    v.w = fmaxf(0.f, v.w * sc.w + sh.w);
    ((float4*)out)[i] = v;
}

// ============================================================================
extern "C" void kernel_launch(void* const* d_in, const int* in_sizes, int n_in,
                              void* d_out, int out_size)
{
    const float* x    = (const float*)d_in[0];
    const int*   ei   = (const int*)  d_in[1];
    const float* Wlin = (const float*)d_in[2];
    const float* blin = (const float*)d_in[3];
    const float* pw   = (const float*)d_in[4];
    const float* Wgat = (const float*)d_in[5];
    const float* attS = (const float*)d_in[6];
    const float* attD = (const float*)d_in[7];
    // d_in[8] = gat_bias: cancels under batch-stat BatchNorm.
    const float* gamma = (const float*)d_in[9];
    const float* beta  = (const float*)d_in[10];
    float* out = (float*)d_out;

    int n = in_sizes[0] / D;     // 50000
    int e = in_sizes[1] / 2;     // 800000
    const int* srcA = ei;
    const int* dstA = ei + e;

    static int inited = 0;
    if (!inited) {
        cudaFuncSetAttribute(k_linear2, cudaFuncAttributeMaxDynamicSharedMemorySize, K1_SMEM);
        inited = 1;
    }

    int nch = (n + 511) / 512;

    k_prep_vec<<<1, 256>>>(Wgat, attS, attD);                                // 0
    k_zero<<<200, 256>>>(n);                                                 // 1
    k_zero_sums<<<1, 128>>>();                                               // 2
    k_linear2<<<(n + 63) / 64, 256, K1_SMEM>>>(x, Wlin, blin, pw, Wgat,
                                               dstA, n, e);                  // 3 (profiled)
    k_scanA<<<nch, 512>>>(n);                                                // 4
    k_scanB<<<1, 256>>>(nch);                                                // 5
    k_scanC<<<(n + 255) / 256, 256>>>(n, e);                                 // 6
    k_edgeW<<<(e + n + 255) / 256, 256>>>(srcA, dstA, n, e);                 // 7
    k_gather<<<(n * 32 + 255) / 256, 256>>>(out, n);                         // 8
    k_bnstats<<<200, 256>>>(out, n);                                         // 9
    k_bnprep<<<1, 64>>>(gamma, beta, n);                                     // 10
    k_bnfinal<<<(n * 16 + 255) / 256, 256>>>(out, n);                        // 11
}

// round 7
// speedup vs baseline: 1.0293x; 1.0293x over previous
#include <cuda_runtime.h>
#include <cuda_fp16.h>
#include <mma.h>
#include <cstdint>
#include <cstddef>

using namespace nvcuda;

#define D   64
#define H   4
#define NEG 0.2f
#define BN_EPS 1e-5f

#define NMAX 50000
#define EMAX 800000

// ---------------- scratch (static device globals; no allocation) ----------------
__device__ __half  g_hh[(size_t)NMAX * 256];    // [N][head][dim] fp16 features
__device__ float  g_asrc[NMAX * H];
__device__ float  g_adst[NMAX * H];
__device__ float  g_wcsr[(size_t)EMAX * H];     // per-edge weights (CSR order)
__device__ float  g_wself[NMAX * H];
__device__ float  g_dnm[NMAX * H];              // softmax denominators (atomic)
__device__ float  g_cs[H * D];                  // W_gat_h^T att_src_h
__device__ float  g_cd[H * D];                  // W_gat_h^T att_dst_h
__device__ int    g_cnt[NMAX];
__device__ int    g_rowptr[NMAX + 1];
__device__ int    g_cursor[NMAX];
__device__ int    g_csrc[EMAX];
__device__ int    g_bsum[256];
__device__ double g_sums[128];                  // [0:64) sum, [64:128) sumsq
__device__ float  g_bnsc[64], g_bnsh[64];

// ---------------- fast exp: FMA polynomial (no MUFU) ----------------
__device__ __forceinline__ float fexp(float x) {
    x = fmaxf(x, -80.f);
    float y  = x * 1.44269504089f;
    float t  = y + 12582912.0f;
    int   ki = __float_as_int(t) - 0x4B400000;
    float r  = y - (t - 12582912.0f);
    float p  = 1.5403530e-4f;
    p = fmaf(p, r, 1.3333558e-3f);
    p = fmaf(p, r, 9.6181291e-3f);
    p = fmaf(p, r, 5.5504109e-2f);
    p = fmaf(p, r, 2.4022651e-1f);
    p = fmaf(p, r, 6.9314718e-1f);
    p = fmaf(p, r, 1.0f);
    return __int_as_float(__float_as_int(p) + (ki << 23));
}

__device__ __forceinline__ float lrelu(float v) { return (v >= 0.f) ? v : NEG * v; }

__device__ __forceinline__ float sel4(float4 v, int h) {
    float r = v.x;
    r = (h == 1) ? v.y : r;
    r = (h == 2) ? v.z : r;
    r = (h == 3) ? v.w : r;
    return r;
}

// ============================================================================
// prep kernels (3 tiny launches so launch #4 = k_linear2 gets profiled)
// ============================================================================
__global__ void k_prep_vec(const float* __restrict__ Wgat,
                           const float* __restrict__ attS,
                           const float* __restrict__ attD) {
    int tid = threadIdx.x;              // 256
    int h = tid >> 6, k = tid & 63;
    float s = 0.f, d2 = 0.f;
    #pragma unroll 8
    for (int dd = 0; dd < 64; dd++) {
        float wv = Wgat[(h * 64 + dd) * 64 + k];
        s  += attS[h * 64 + dd] * wv;
        d2 += attD[h * 64 + dd] * wv;
    }
    g_cs[tid] = s;
    g_cd[tid] = d2;
}

__global__ void k_zero(int n) {
    int gid = blockIdx.x * blockDim.x + threadIdx.x;
    int stride = gridDim.x * blockDim.x;
    for (int i = gid; i < n; i += stride) g_cnt[i] = 0;
    for (int i = gid; i < n * 4; i += stride) g_dnm[i] = 0.f;
}

__global__ void k_zero_sums() {
    if (threadIdx.x < 128) g_sums[threadIdx.x] = 0.0;
}

// ============================================================================
// K1: fused  u = PReLU(x W_lin^T + b) [FFMA];  h = u W_gat^T [wmma HMMA fp16];
//     a_src/a_dst dots;  + destination histogram (overlapped)
//
// smem layout (floats):
//   [0, 4608)          sX [64][72]  (stage A); later per-warp epilogue staging
//   [4608, 9216)       sU [64][72]  fp32 (attention dots)
//   [9216, 9760)       sC, sC2 [4][68]
//   [9760, 17952)      stage A: Wlin fp32 [64][72]; stage B: W_gat fp16 [256][64]
//   [17952, 20256)     sUh fp16 [64][72]
// ============================================================================
#define K1_FLOATS 20256
#define K1_SMEM   (K1_FLOATS * 4)

__global__ __launch_bounds__(256, 2) void k_linear2(
    const float* __restrict__ x, const float* __restrict__ Wlin,
    const float* __restrict__ blin, const float* __restrict__ pw,
    const float* __restrict__ Wgat, const int* __restrict__ dstA,
    int nrows, int nedges)
{
    extern __shared__ float sm[];
    float*  sX  = sm;                         // [64][72]
    float*  sU  = sm + 4608;                  // [64][72]
    float*  sC  = sm + 9216;                  // [4][68]
    float*  sC2 = sm + 9216 + 272;            // [4][68]
    float*  sWf = sm + 9760;                  // Wlin fp32 [64][72] (stage A)
    __half* sWh = (__half*)(sm + 9760);       // W_gat fp16 [256][64] (stage B)
    __half* sUh = (__half*)(sm + 17952);      // u fp16 [64][72]
    const int tid  = threadIdx.x;
    const int row0 = blockIdx.x * 64;

    // destination histogram (independent, overlaps FFMA work)
    {
        int gid = blockIdx.x * 256 + tid;
        int stride = gridDim.x * 256;
        for (int i = gid; i < nedges; i += stride)
            atomicAdd(&g_cnt[dstA[i]], 1);
    }

    {
        int h = tid >> 6, k = tid & 63;
        sC [h * 68 + k] = g_cs[tid];
        sC2[h * 68 + k] = g_cd[tid];
    }
    for (int i = tid; i < 64 * 64; i += 256) {
        int r = i >> 6, k = i & 63;
        int gr = row0 + r;
        sX[k * 72 + r] = (gr < nrows) ? x[(size_t)gr * D + k] : 0.f;
    }
    for (int i = tid; i < 64 * 64; i += 256) {
        int j = i >> 6, k = i & 63;
        sWf[k * 72 + j] = Wlin[i];
    }
    __syncthreads();

    // ---- stage A: u = PReLU(x W_lin^T + b) -> sU (fp32, [k][r]) + sUh (fp16, [r][k]) ----
    {
        const int rg = (tid >> 4) << 2;
        const int cg = (tid & 15) << 2;
        float acc[4][4];
        #pragma unroll
        for (int a = 0; a < 4; a++)
            #pragma unroll
            for (int b = 0; b < 4; b++) acc[a][b] = 0.f;
        #pragma unroll 8
        for (int k = 0; k < 64; k++) {
            float4 a4 = *(const float4*)(sX + k * 72 + rg);
            float4 b4 = *(const float4*)(sWf + k * 72 + cg);
            float av[4] = {a4.x, a4.y, a4.z, a4.w};
            float bv[4] = {b4.x, b4.y, b4.z, b4.w};
            #pragma unroll
            for (int ri = 0; ri < 4; ri++)
                #pragma unroll
                for (int cj = 0; cj < 4; cj++) acc[ri][cj] += av[ri] * bv[cj];
        }
        float4 bb = *(const float4*)(blin + cg);
        float4 pp = *(const float4*)(pw + cg);
        float bvb[4] = {bb.x, bb.y, bb.z, bb.w};
        float pvb[4] = {pp.x, pp.y, pp.z, pp.w};
        #pragma unroll
        for (int ri = 0; ri < 4; ri++)
            #pragma unroll
            for (int cj = 0; cj < 4; cj++) {
                float v = acc[ri][cj] + bvb[cj];
                v = (v >= 0.f) ? v : pvb[cj] * v;
                sU[(cg + cj) * 72 + rg + ri] = v;
                sUh[(rg + ri) * 72 + cg + cj] = __float2half_rn(v);
            }
    }
    __syncthreads();   // stage A readers of sWf done; sUh complete

    // load W_gat as fp16 into sWh [m=256][k=64] (contiguous copy)
    {
        half2* sWh2 = (half2*)sWh;
        for (int i = tid; i < 8192; i += 256) {
            float2 wv = ((const float2*)Wgat)[i];
            sWh2[i] = __float22half2_rn(wv);
        }
    }
    __syncthreads();

    // ---- stage B: h = u W_gat^T via wmma (each warp: 16 rows x 128 cols) ----
    {
        const int wid  = tid >> 5;
        const int lane = tid & 31;
        const int rowg = (wid >> 1) << 4;     // 0,16,32,48
        const int colg = (wid & 1) << 7;      // 0 or 128

        wmma::fragment<wmma::accumulator, 16, 16, 16, float> acc[8];
        #pragma unroll
        for (int t = 0; t < 8; t++) wmma::fill_fragment(acc[t], 0.0f);

        #pragma unroll
        for (int ks = 0; ks < 4; ks++) {
            wmma::fragment<wmma::matrix_a, 16, 16, 16, __half, wmma::row_major> af;
            wmma::load_matrix_sync(af, sUh + rowg * 72 + ks * 16, 72);
            #pragma unroll
            for (int ct = 0; ct < 8; ct++) {
                wmma::fragment<wmma::matrix_b, 16, 16, 16, __half, wmma::col_major> bf;
                wmma::load_matrix_sync(bf, sWh + (colg + ct * 16) * 64 + ks * 16, 64);
                wmma::mma_sync(acc[ct], af, bf, acc[ct]);
            }
        }

        // epilogue: per-warp staging (over sX region) -> fp16 [node][head][dim]
        float* stg = sX + wid * 16 * 20;      // 16 rows x ldm 20
        const int srow = lane >> 1;           // 0..15
        const int dcol0 = (lane & 1) * 8;     // 0 or 8
        #pragma unroll
        for (int ct = 0; ct < 8; ct++) {
            wmma::store_matrix_sync(stg, acc[ct], 20, wmma::mem_row_major);
            __syncwarp();
            int c0   = colg + ct * 16;
            int head = c0 >> 6;
            int dim0 = (c0 & 63) + dcol0;
            int node = row0 + rowg + srow;
            if (node < nrows) {
                const float* sp = stg + srow * 20 + dcol0;
                half2 h0 = __floats2half2_rn(sp[0], sp[1]);
                half2 h1 = __floats2half2_rn(sp[2], sp[3]);
                half2 h2 = __floats2half2_rn(sp[4], sp[5]);
                half2 h3 = __floats2half2_rn(sp[6], sp[7]);
                uint4 pk;
                pk.x = *(unsigned*)&h0; pk.y = *(unsigned*)&h1;
                pk.z = *(unsigned*)&h2; pk.w = *(unsigned*)&h3;
                *(uint4*)(g_hh + (size_t)node * 256 + head * 64 + dim0) = pk;
            }
            __syncwarp();
        }
    }

    // attention dots from fp32 sU (untouched by stage B)
    {
        const int r = tid >> 2, h = tid & 3;
        float sa = 0.f, da = 0.f;
        #pragma unroll 8
        for (int k = 0; k < 64; k++) {
            float uv = sU[k * 72 + r];
            sa += uv * sC [h * 68 + k];
            da += uv * sC2[h * 68 + k];
        }
        int gr = row0 + r;
        if (gr < nrows) {
            g_asrc[gr * 4 + h] = sa;
            g_adst[gr * 4 + h] = da;
        }
    }
}

// ============================================================================
// scan
// ============================================================================
__global__ void k_scanA(int n) {
    __shared__ int sh[512];
    int i = blockIdx.x * 512 + threadIdx.x;
    int v = (i < n) ? g_cnt[i] : 0;
    sh[threadIdx.x] = v;
    __syncthreads();
    #pragma unroll
    for (int off = 1; off < 512; off <<= 1) {
        int t = (threadIdx.x >= off) ? sh[threadIdx.x - off] : 0;
        __syncthreads();
        sh[threadIdx.x] += t;
        __syncthreads();
    }
    if (i < n) g_rowptr[i] = sh[threadIdx.x] - v;
    if (threadIdx.x == 511) g_bsum[blockIdx.x] = sh[511];
}

__global__ void k_scanB(int nch) {
    __shared__ int sh[256];
    int v = (threadIdx.x < nch) ? g_bsum[threadIdx.x] : 0;
    sh[threadIdx.x] = v;
    __syncthreads();
    #pragma unroll
    for (int off = 1; off < 256; off <<= 1) {
        int t = (threadIdx.x >= off) ? sh[threadIdx.x - off] : 0;
        __syncthreads();
        sh[threadIdx.x] += t;
        __syncthreads();
    }
    if (threadIdx.x < nch) g_bsum[threadIdx.x] = sh[threadIdx.x] - v;
}

__global__ void k_scanC(int n, int e) {
    int i = blockIdx.x * blockDim.x + threadIdx.x;
    if (i < n) {
        int v = g_rowptr[i] + g_bsum[i >> 9];
        g_rowptr[i] = v;
        g_cursor[i] = v;
    }
    if (i == 0) g_rowptr[n] = e;
}

// ============================================================================
// K2: fused edge weights + CSR scatter (no max pass; magnitudes bounded).
// ============================================================================
__global__ __launch_bounds__(256) void k_edgeW(const int* __restrict__ src,
                                               const int* __restrict__ dst,
                                               int n, int e)
{
    int i = blockIdx.x * 256 + threadIdx.x;
    if (i < e) {
        int s = src[i], d = dst[i];
        float4 a = ((const float4*)g_asrc)[s];
        float4 b = ((const float4*)g_adst)[d];
        float4 w = make_float4(fexp(lrelu(a.x + b.x)), fexp(lrelu(a.y + b.y)),
                               fexp(lrelu(a.z + b.z)), fexp(lrelu(a.w + b.w)));
        int pos = atomicAdd(&g_cursor[d], 1);
        g_csrc[pos] = s;
        ((float4*)g_wcsr)[pos] = w;
        float* dn = g_dnm + d * 4;
        atomicAdd(dn + 0, w.x);
        atomicAdd(dn + 1, w.y);
        atomicAdd(dn + 2, w.z);
        atomicAdd(dn + 3, w.w);
    } else if (i < e + n) {
        int v = i - e;
        float4 a = ((const float4*)g_asrc)[v];
        float4 b = ((const float4*)g_adst)[v];
        float4 w = make_float4(fexp(lrelu(a.x + b.x)), fexp(lrelu(a.y + b.y)),
                               fexp(lrelu(a.z + b.z)), fexp(lrelu(a.w + b.w)));
        ((float4*)g_wself)[v] = w;
        float* dn = g_dnm + v * 4;
        atomicAdd(dn + 0, w.x);
        atomicAdd(dn + 1, w.y);
        atomicAdd(dn + 2, w.z);
        atomicAdd(dn + 3, w.w);
    }
}

// ============================================================================
// K4: warp-per-node weighted gather. Lane = (head = lane>>3, 8 dims).
//     One LDG.128 per lane per source row; butterfly head-sum at end.
// ============================================================================
__global__ __launch_bounds__(256) void k_gather(float* __restrict__ out, int n)
{
    int gw = (blockIdx.x * blockDim.x + threadIdx.x) >> 5;
    if (gw >= n) return;
    const int lane = threadIdx.x & 31;
    const int hh = lane >> 3;

    float4 wsv = ((const float4*)g_wself)[gw];
    float ws = sel4(wsv, hh);
    uint4 hv = ((const uint4*)(g_hh + (size_t)gw * 256))[lane];
    float2 f0 = __half22float2(*(__half2*)&hv.x);
    float2 f1 = __half22float2(*(__half2*)&hv.y);
    float2 f2 = __half22float2(*(__half2*)&hv.z);
    float2 f3 = __half22float2(*(__half2*)&hv.w);
    float A0 = ws * f0.x, A1 = ws * f0.y, A2 = ws * f1.x, A3 = ws * f1.y;
    float A4 = ws * f2.x, A5 = ws * f2.y, A6 = ws * f3.x, A7 = ws * f3.y;

    const int eb = g_rowptr[gw], ee = g_rowptr[gw + 1];
    #pragma unroll 2
    for (int e = eb; e < ee; e++) {
        int src  = g_csrc[e];
        float4 w4 = ((const float4*)g_wcsr)[e];
        float w = sel4(w4, hh);
        uint4 sv = ((const uint4*)(g_hh + (size_t)src * 256))[lane];
        float2 b0 = __half22float2(*(__half2*)&sv.x);
        float2 b1 = __half22float2(*(__half2*)&sv.y);
        float2 b2 = __half22float2(*(__half2*)&sv.z);
        float2 b3 = __half22float2(*(__half2*)&sv.w);
        A0 = fmaf(w, b0.x, A0); A1 = fmaf(w, b0.y, A1);
        A2 = fmaf(w, b1.x, A2); A3 = fmaf(w, b1.y, A3);
        A4 = fmaf(w, b2.x, A4); A5 = fmaf(w, b2.y, A5);
        A6 = fmaf(w, b3.x, A6); A7 = fmaf(w, b3.y, A7);
    }

    float4 dnv = ((const float4*)g_dnm)[gw];
    float ih = 0.25f / sel4(dnv, hh);
    A0 *= ih; A1 *= ih; A2 *= ih; A3 *= ih;
    A4 *= ih; A5 *= ih; A6 *= ih; A7 *= ih;

    // sum the 4 heads: lanes differing in bits 3,4 hold the same dims
    #pragma unroll
    for (int off = 8; off <= 16; off <<= 1) {
        A0 += __shfl_xor_sync(0xffffffffu, A0, off);
        A1 += __shfl_xor_sync(0xffffffffu, A1, off);
        A2 += __shfl_xor_sync(0xffffffffu, A2, off);
        A3 += __shfl_xor_sync(0xffffffffu, A3, off);
        A4 += __shfl_xor_sync(0xffffffffu, A4, off);
        A5 += __shfl_xor_sync(0xffffffffu, A5, off);
        A6 += __shfl_xor_sync(0xffffffffu, A6, off);
        A7 += __shfl_xor_sync(0xffffffffu, A7, off);
    }
    if (lane < 8) {
        float* op = out + (size_t)gw * 64 + lane * 8;
        *(float4*)(op)     = make_float4(A0, A1, A2, A3);
        *(float4*)(op + 4) = make_float4(A4, A5, A6, A7);
    }
}

// ============================================================================
// BatchNorm (batch stats; gat_bias cancels) + ReLU
// ============================================================================
__global__ void k_bnstats(const float* __restrict__ out, int nnodes) {
    __shared__ double shs[256], shq[256];
    const int c = threadIdx.x & 63;
    const int g = threadIdx.x >> 6;
    double s = 0.0, q = 0.0;
    for (int r = blockIdx.x * 4 + g; r < nnodes; r += gridDim.x * 4) {
        float v = out[(size_t)r * D + c];
        s += v;
        q += (double)v * v;
    }
    shs[threadIdx.x] = s; shq[threadIdx.x] = q;
    __syncthreads();
    if (g == 0) {
        s = shs[c] + shs[c + 64] + shs[c + 128] + shs[c + 192];
        q = shq[c] + shq[c + 64] + shq[c + 128] + shq[c + 192];
        atomicAdd(&g_sums[c], s);
        atomicAdd(&g_sums[64 + c], q);
    }
}

__global__ void k_bnprep(const float* __restrict__ gamma,
                         const float* __restrict__ beta, int nnodes) {
    int c = threadIdx.x;
    if (c < 64) {
        double mean = g_sums[c] / nnodes;
        double var  = g_sums[64 + c] / nnodes - mean * mean;
        float scale = gamma[c] * rsqrtf((float)var + BN_EPS);
        g_bnsc[c] = scale;
        g_bnsh[c] = beta[c] - (float)mean * scale;
    }
}

__global__ void k_bnfinal(float* __restrict__ out, int nnodes) {
    int i = blockIdx.x * blockDim.x + threadIdx.x;
    int total = nnodes * 16;
    if (i >= total) return;
    int c4 = (i & 15) << 2;
    float4 v = ((float4*)out)[i];
    float4 sc = *(const float4*)(g_bnsc + c4);
    float4 sh = *(const float4*)(g_bnsh + c4);
    v.x = fmaxf(0.f, v.x * sc.x + sh.x);
    v.y = fmaxf(0.f, v.y * sc.y + sh.y);
    v.z = fmaxf(0.f, v.z * sc.z + sh.z);
    v.w = fmaxf(0.f, v.w * sc.w + sh.w);
    ((float4*)out)[i] = v;
}

// ============================================================================
extern "C" void kernel_launch(void* const* d_in, const int* in_sizes, int n_in,
                              void* d_out, int out_size)
{
    const float* x    = (const float*)d_in[0];
    const int*   ei   = (const int*)  d_in[1];
    const float* Wlin = (const float*)d_in[2];
    const float* blin = (const float*)d_in[3];
    const float* pw   = (const float*)d_in[4];
    const float* Wgat = (const float*)d_in[5];
    const float* attS = (const float*)d_in[6];
    const float* attD = (const float*)d_in[7];
    // d_in[8] = gat_bias: cancels under batch-stat BatchNorm.
    const float* gamma = (const float*)d_in[9];
    const float* beta  = (const float*)d_in[10];
    float* out = (float*)d_out;

    int n = in_sizes[0] / D;     // 50000
    int e = in_sizes[1] / 2;     // 800000
    const int* srcA = ei;
    const int* dstA = ei + e;

    static int inited = 0;
    if (!inited) {
        cudaFuncSetAttribute(k_linear2, cudaFuncAttributeMaxDynamicSharedMemorySize, K1_SMEM);
        inited = 1;
    }

    int nch = (n + 511) / 512;

    k_prep_vec<<<1, 256>>>(Wgat, attS, attD);                                // 0
    k_zero<<<200, 256>>>(n);                                                 // 1
    k_zero_sums<<<1, 128>>>();                                               // 2
    k_linear2<<<(n + 63) / 64, 256, K1_SMEM>>>(x, Wlin, blin, pw, Wgat,
                                               dstA, n, e);                  // 3 (profiled)
    k_scanA<<<nch, 512>>>(n);                                                // 4
    k_scanB<<<1, 256>>>(nch);                                                // 5
    k_scanC<<<(n + 255) / 256, 256>>>(n, e);                                 // 6
    k_edgeW<<<(e + n + 255) / 256, 256>>>(srcA, dstA, n, e);                 // 7
    k_gather<<<(n * 32 + 255) / 256, 256>>>(out, n);                         // 8
    k_bnstats<<<200, 256>>>(out, n);                                         // 9
    k_bnprep<<<1, 64>>>(gamma, beta, n);                                     // 10
    k_bnfinal<<<(n * 16 + 255) / 256, 256>>>(out, n);                        // 11
}

// round 8
// speedup vs baseline: 1.0395x; 1.0099x over previous
#include <cuda_runtime.h>
#include <cuda_fp16.h>
#include <mma.h>
#include <cstdint>
#include <cstddef>

using namespace nvcuda;

#define D   64
#define H   4
#define NEG 0.2f
#define BN_EPS 1e-5f

#define NMAX 50000
#define EMAX 800000

// ---------------- scratch (static device globals; no allocation) ----------------
__device__ __half  g_uh[(size_t)NMAX * 64];     // [N][64] fp16 post-PReLU features
__device__ __half  g_hh[(size_t)NMAX * 256];    // [N][head][dim] fp16 GAT features
__device__ float  g_asrc[NMAX * H];
__device__ float  g_adst[NMAX * H];
__device__ float  g_wcsr[(size_t)EMAX * H];     // per-edge weights (CSR order)
__device__ float  g_wself[NMAX * H];
__device__ float  g_dnm[NMAX * H];              // softmax denominators (atomic)
__device__ float  g_cs[H * D];                  // W_gat_h^T att_src_h
__device__ float  g_cd[H * D];                  // W_gat_h^T att_dst_h
__device__ int    g_cnt[NMAX];
__device__ int    g_rowptr[NMAX + 1];
__device__ int    g_cursor[NMAX];
__device__ int    g_csrc[EMAX];
__device__ int    g_bsum[256];
__device__ double g_sums[128];                  // [0:64) sum, [64:128) sumsq
__device__ float  g_bnsc[64], g_bnsh[64];

// ---------------- fast exp: FMA polynomial (no MUFU) ----------------
__device__ __forceinline__ float fexp(float x) {
    x = fmaxf(x, -80.f);
    float y  = x * 1.44269504089f;
    float t  = y + 12582912.0f;
    int   ki = __float_as_int(t) - 0x4B400000;
    float r  = y - (t - 12582912.0f);
    float p  = 1.5403530e-4f;
    p = fmaf(p, r, 1.3333558e-3f);
    p = fmaf(p, r, 9.6181291e-3f);
    p = fmaf(p, r, 5.5504109e-2f);
    p = fmaf(p, r, 2.4022651e-1f);
    p = fmaf(p, r, 6.9314718e-1f);
    p = fmaf(p, r, 1.0f);
    return __int_as_float(__float_as_int(p) + (ki << 23));
}

__device__ __forceinline__ float lrelu(float v) { return (v >= 0.f) ? v : NEG * v; }

__device__ __forceinline__ float sel4(float4 v, int h) {
    float r = v.x;
    r = (h == 1) ? v.y : r;
    r = (h == 2) ? v.z : r;
    r = (h == 3) ? v.w : r;
    return r;
}

// ============================================================================
// prep
// ============================================================================
__global__ void k_prep_vec(const float* __restrict__ Wgat,
                           const float* __restrict__ attS,
                           const float* __restrict__ attD) {
    int tid = threadIdx.x;              // 256
    int h = tid >> 6, k = tid & 63;
    float s = 0.f, d2 = 0.f;
    #pragma unroll 8
    for (int dd = 0; dd < 64; dd++) {
        float wv = Wgat[(h * 64 + dd) * 64 + k];
        s  += attS[h * 64 + dd] * wv;
        d2 += attD[h * 64 + dd] * wv;
    }
    g_cs[tid] = s;
    g_cd[tid] = d2;
}

__global__ void k_zero(int n) {
    int gid = blockIdx.x * blockDim.x + threadIdx.x;
    int stride = gridDim.x * blockDim.x;
    for (int i = gid; i < n; i += stride) g_cnt[i] = 0;
    for (int i = gid; i < n * 4; i += stride) g_dnm[i] = 0.f;
    if (blockIdx.x == 0 && threadIdx.x < 128) g_sums[threadIdx.x] = 0.0;
}

// ============================================================================
// K_A: u = PReLU(x W_lin^T + b) -> g_uh (fp16);  a_src/a_dst dots;  histogram.
// 64 rows/block, 256 threads, ~48KB smem (sU aliases sX) -> 4 CTAs/SM.
// ============================================================================
#define KA_FLOATS (4608 + 4608 + 2*68*4 + 2304)
#define KA_SMEM   (KA_FLOATS * 4)

__global__ __launch_bounds__(256) void k_ulinear(
    const float* __restrict__ x, const float* __restrict__ Wlin,
    const float* __restrict__ blin, const float* __restrict__ pw,
    const int* __restrict__ dstA, int nrows, int nedges)
{
    extern __shared__ float sm[];
    float*  sX  = sm;                        // [64][72] x tile; later aliased by sU
    float*  sU  = sm;                        // [col][row] u fp32 (alias of sX)
    float*  sW  = sm + 4608;                 // [64][72] Wlin^T
    float*  sC  = sm + 9216;                 // [4][68]
    float*  sC2 = sm + 9216 + 272;           // [4][68]
    __half* sUh = (__half*)(sm + 9760);      // [row][72] u fp16
    const int tid  = threadIdx.x;
    const int row0 = blockIdx.x * 64;

    // destination histogram (independent, overlaps)
    {
        int gid = blockIdx.x * 256 + tid;
        int stride = gridDim.x * 256;
        for (int i = gid; i < nedges; i += stride)
            atomicAdd(&g_cnt[dstA[i]], 1);
    }

    {
        int h = tid >> 6, k = tid & 63;
        sC [h * 68 + k] = g_cs[tid];
        sC2[h * 68 + k] = g_cd[tid];
    }
    for (int i = tid; i < 64 * 64; i += 256) {
        int r = i >> 6, k = i & 63;
        int gr = row0 + r;
        sX[k * 72 + r] = (gr < nrows) ? x[(size_t)gr * D + k] : 0.f;
    }
    for (int i = tid; i < 64 * 64; i += 256) {
        int j = i >> 6, k = i & 63;
        sW[k * 72 + j] = Wlin[i];
    }
    __syncthreads();

    // stage A microkernel (4x4)
    float accv[4][4];
    {
        const int rg = (tid >> 4) << 2;
        const int cg = (tid & 15) << 2;
        #pragma unroll
        for (int a = 0; a < 4; a++)
            #pragma unroll
            for (int b = 0; b < 4; b++) accv[a][b] = 0.f;
        #pragma unroll 8
        for (int k = 0; k < 64; k++) {
            float4 a4 = *(const float4*)(sX + k * 72 + rg);
            float4 b4 = *(const float4*)(sW + k * 72 + cg);
            float av[4] = {a4.x, a4.y, a4.z, a4.w};
            float bv[4] = {b4.x, b4.y, b4.z, b4.w};
            #pragma unroll
            for (int ri = 0; ri < 4; ri++)
                #pragma unroll
                for (int cj = 0; cj < 4; cj++) accv[ri][cj] += av[ri] * bv[cj];
        }
    }
    __syncthreads();   // all reads of sX done; safe to alias with sU

    {
        const int rg = (tid >> 4) << 2;
        const int cg = (tid & 15) << 2;
        float4 bb = *(const float4*)(blin + cg);
        float4 pp = *(const float4*)(pw + cg);
        float bvb[4] = {bb.x, bb.y, bb.z, bb.w};
        float pvb[4] = {pp.x, pp.y, pp.z, pp.w};
        #pragma unroll
        for (int ri = 0; ri < 4; ri++)
            #pragma unroll
            for (int cj = 0; cj < 4; cj++) {
                float v = accv[ri][cj] + bvb[cj];
                v = (v >= 0.f) ? v : pvb[cj] * v;
                sU[(cg + cj) * 72 + rg + ri]  = v;
                sUh[(rg + ri) * 72 + cg + cj] = __float2half_rn(v);
            }
    }
    __syncthreads();

    // att dots from fp32 sU
    {
        const int r = tid >> 2, h = tid & 3;
        float sa = 0.f, da = 0.f;
        #pragma unroll 8
        for (int k = 0; k < 64; k++) {
            float uv = sU[k * 72 + r];
            sa += uv * sC [h * 68 + k];
            da += uv * sC2[h * 68 + k];
        }
        int gr = row0 + r;
        if (gr < nrows) {
            g_asrc[gr * 4 + h] = sa;
            g_adst[gr * 4 + h] = da;
        }
    }

    // coalesced fp16 u store (uint4 = 8 halves)
    for (int i = tid; i < 512; i += 256) {
        int r = i >> 3, q = i & 7;
        int gr = row0 + r;
        if (gr < nrows)
            *(uint4*)(g_uh + (size_t)gr * 64 + q * 8) =
                *(const uint4*)(sUh + r * 72 + q * 8);
    }
}

// ============================================================================
// K_B: h = u W_gat^T via wmma fp16. 64 rows/block, 256 threads, 1 barrier.
// smem: sUh [64][72] fp16 | sWh [256][64] fp16 | stg 8*16*20 fp32  (~52KB)
// ============================================================================
#define KB_FLOATS (2304 + 8192 + 2560)
#define KB_SMEM   (KB_FLOATS * 4)

__global__ __launch_bounds__(256) void k_hgemm(const float* __restrict__ Wgat,
                                               int nrows)
{
    extern __shared__ float sm[];
    __half* sUh = (__half*)sm;                // [64][72]
    __half* sWh = (__half*)(sm + 2304);       // [256][64]
    float*  stg = sm + 2304 + 8192;           // 8 warps x 16 x 20
    const int tid  = threadIdx.x;
    const int row0 = blockIdx.x * 64;

    // load u tile (fp16, already rounded)
    {
        int rmax = nrows - row0;
        for (int i = tid; i < 512; i += 256) {
            int r = i >> 3, q = i & 7;
            uint4 v = make_uint4(0u, 0u, 0u, 0u);
            if (r < rmax) v = *(const uint4*)(g_uh + (size_t)(row0 + r) * 64 + q * 8);
            *(uint4*)(sUh + r * 72 + q * 8) = v;
        }
    }
    // load W_gat fp32 -> fp16 [m][k] contiguous
    {
        half2* sWh2 = (half2*)sWh;
        for (int i = tid; i < 8192; i += 256) {
            float2 wv = ((const float2*)Wgat)[i];
            sWh2[i] = __float22half2_rn(wv);
        }
    }
    __syncthreads();

    const int wid  = tid >> 5;
    const int lane = tid & 31;
    const int rowg = (wid >> 1) << 4;     // 0,16,32,48
    const int colg = (wid & 1) << 7;      // 0 or 128

    wmma::fragment<wmma::accumulator, 16, 16, 16, float> acc[8];
    #pragma unroll
    for (int t = 0; t < 8; t++) wmma::fill_fragment(acc[t], 0.0f);

    #pragma unroll
    for (int ks = 0; ks < 4; ks++) {
        wmma::fragment<wmma::matrix_a, 16, 16, 16, __half, wmma::row_major> af;
        wmma::load_matrix_sync(af, sUh + rowg * 72 + ks * 16, 72);
        #pragma unroll
        for (int ct = 0; ct < 8; ct++) {
            wmma::fragment<wmma::matrix_b, 16, 16, 16, __half, wmma::col_major> bf;
            wmma::load_matrix_sync(bf, sWh + (colg + ct * 16) * 64 + ks * 16, 64);
            wmma::mma_sync(acc[ct], af, bf, acc[ct]);
        }
    }

    // epilogue via per-warp staging -> fp16 [node][head][dim]
    float* ws = stg + wid * 320;          // 16 rows x ldm 20
    const int srow  = lane >> 1;
    const int dcol0 = (lane & 1) * 8;
    #pragma unroll
    for (int ct = 0; ct < 8; ct++) {
        wmma::store_matrix_sync(ws, acc[ct], 20, wmma::mem_row_major);
        __syncwarp();
        int c0   = colg + ct * 16;
        int head = c0 >> 6;
        int dim0 = (c0 & 63) + dcol0;
        int node = row0 + rowg + srow;
        if (node < nrows) {
            const float* sp = ws + srow * 20 + dcol0;
            half2 h0 = __floats2half2_rn(sp[0], sp[1]);
            half2 h1 = __floats2half2_rn(sp[2], sp[3]);
            half2 h2 = __floats2half2_rn(sp[4], sp[5]);
            half2 h3 = __floats2half2_rn(sp[6], sp[7]);
            uint4 pk;
            pk.x = *(unsigned*)&h0; pk.y = *(unsigned*)&h1;
            pk.z = *(unsigned*)&h2; pk.w = *(unsigned*)&h3;
            *(uint4*)(g_hh + (size_t)node * 256 + head * 64 + dim0) = pk;
        }
        __syncwarp();
    }
}

// ============================================================================
// scan
// ============================================================================
__global__ void k_scanA(int n) {
    __shared__ int sh[512];
    int i = blockIdx.x * 512 + threadIdx.x;
    int v = (i < n) ? g_cnt[i] : 0;
    sh[threadIdx.x] = v;
    __syncthreads();
    #pragma unroll
    for (int off = 1; off < 512; off <<= 1) {
        int t = (threadIdx.x >= off) ? sh[threadIdx.x - off] : 0;
        __syncthreads();
        sh[threadIdx.x] += t;
        __syncthreads();
    }
    if (i < n) g_rowptr[i] = sh[threadIdx.x] - v;
    if (threadIdx.x == 511) g_bsum[blockIdx.x] = sh[511];
}

__global__ void k_scanB(int nch) {
    __shared__ int sh[256];
    int v = (threadIdx.x < nch) ? g_bsum[threadIdx.x] : 0;
    sh[threadIdx.x] = v;
    __syncthreads();
    #pragma unroll
    for (int off = 1; off < 256; off <<= 1) {
        int t = (threadIdx.x >= off) ? sh[threadIdx.x - off] : 0;
        __syncthreads();
        sh[threadIdx.x] += t;
        __syncthreads();
    }
    if (threadIdx.x < nch) g_bsum[threadIdx.x] = sh[threadIdx.x] - v;
}

__global__ void k_scanC(int n, int e) {
    int i = blockIdx.x * blockDim.x + threadIdx.x;
    if (i < n) {
        int v = g_rowptr[i] + g_bsum[i >> 9];
        g_rowptr[i] = v;
        g_cursor[i] = v;
    }
    if (i == 0) g_rowptr[n] = e;
}

// ============================================================================
// K2: fused edge weights + CSR scatter
// ============================================================================
__global__ __launch_bounds__(256) void k_edgeW(const int* __restrict__ src,
                                               const int* __restrict__ dst,
                                               int n, int e)
{
    int i = blockIdx.x * 256 + threadIdx.x;
    if (i < e) {
        int s = src[i], d = dst[i];
        float4 a = ((const float4*)g_asrc)[s];
        float4 b = ((const float4*)g_adst)[d];
        float4 w = make_float4(fexp(lrelu(a.x + b.x)), fexp(lrelu(a.y + b.y)),
                               fexp(lrelu(a.z + b.z)), fexp(lrelu(a.w + b.w)));
        int pos = atomicAdd(&g_cursor[d], 1);
        g_csrc[pos] = s;
        ((float4*)g_wcsr)[pos] = w;
        float* dn = g_dnm + d * 4;
        atomicAdd(dn + 0, w.x);
        atomicAdd(dn + 1, w.y);
        atomicAdd(dn + 2, w.z);
        atomicAdd(dn + 3, w.w);
    } else if (i < e + n) {
        int v = i - e;
        float4 a = ((const float4*)g_asrc)[v];
        float4 b = ((const float4*)g_adst)[v];
        float4 w = make_float4(fexp(lrelu(a.x + b.x)), fexp(lrelu(a.y + b.y)),
                               fexp(lrelu(a.z + b.z)), fexp(lrelu(a.w + b.w)));
        ((float4*)g_wself)[v] = w;
        float* dn = g_dnm + v * 4;
        atomicAdd(dn + 0, w.x);
        atomicAdd(dn + 1, w.y);
        atomicAdd(dn + 2, w.z);
        atomicAdd(dn + 3, w.w);
    }
}

// ============================================================================
// K4: warp-per-node weighted gather; lane = (head = lane>>3, 8 dims)
// ============================================================================
__global__ __launch_bounds__(256) void k_gather(float* __restrict__ out, int n)
{
    int gw = (blockIdx.x * blockDim.x + threadIdx.x) >> 5;
    if (gw >= n) return;
    const int lane = threadIdx.x & 31;
    const int hh = lane >> 3;

    float4 wsv = ((const float4*)g_wself)[gw];
    float ws = sel4(wsv, hh);
    uint4 hv = ((const uint4*)(g_hh + (size_t)gw * 256))[lane];
    float2 f0 = __half22float2(*(__half2*)&hv.x);
    float2 f1 = __half22float2(*(__half2*)&hv.y);
    float2 f2 = __half22float2(*(__half2*)&hv.z);
    float2 f3 = __half22float2(*(__half2*)&hv.w);
    float A0 = ws * f0.x, A1 = ws * f0.y, A2 = ws * f1.x, A3 = ws * f1.y;
    float A4 = ws * f2.x, A5 = ws * f2.y, A6 = ws * f3.x, A7 = ws * f3.y;

    const int eb = g_rowptr[gw], ee = g_rowptr[gw + 1];
    #pragma unroll 2
    for (int e = eb; e < ee; e++) {
        int src  = g_csrc[e];
        float4 w4 = ((const float4*)g_wcsr)[e];
        float w = sel4(w4, hh);
        uint4 sv = ((const uint4*)(g_hh + (size_t)src * 256))[lane];
        float2 b0 = __half22float2(*(__half2*)&sv.x);
        float2 b1 = __half22float2(*(__half2*)&sv.y);
        float2 b2 = __half22float2(*(__half2*)&sv.z);
        float2 b3 = __half22float2(*(__half2*)&sv.w);
        A0 = fmaf(w, b0.x, A0); A1 = fmaf(w, b0.y, A1);
        A2 = fmaf(w, b1.x, A2); A3 = fmaf(w, b1.y, A3);
        A4 = fmaf(w, b2.x, A4); A5 = fmaf(w, b2.y, A5);
        A6 = fmaf(w, b3.x, A6); A7 = fmaf(w, b3.y, A7);
    }

    float4 dnv = ((const float4*)g_dnm)[gw];
    float ih = 0.25f / sel4(dnv, hh);
    A0 *= ih; A1 *= ih; A2 *= ih; A3 *= ih;
    A4 *= ih; A5 *= ih; A6 *= ih; A7 *= ih;

    #pragma unroll
    for (int off = 8; off <= 16; off <<= 1) {
        A0 += __shfl_xor_sync(0xffffffffu, A0, off);
        A1 += __shfl_xor_sync(0xffffffffu, A1, off);
        A2 += __shfl_xor_sync(0xffffffffu, A2, off);
        A3 += __shfl_xor_sync(0xffffffffu, A3, off);
        A4 += __shfl_xor_sync(0xffffffffu, A4, off);
        A5 += __shfl_xor_sync(0xffffffffu, A5, off);
        A6 += __shfl_xor_sync(0xffffffffu, A6, off);
        A7 += __shfl_xor_sync(0xffffffffu, A7, off);
    }
    if (lane < 8) {
        float* op = out + (size_t)gw * 64 + lane * 8;
        *(float4*)(op)     = make_float4(A0, A1, A2, A3);
        *(float4*)(op + 4) = make_float4(A4, A5, A6, A7);
    }
}

// ============================================================================
// BatchNorm (batch stats; gat_bias cancels) + ReLU
// ============================================================================
__global__ void k_bnstats(const float* __restrict__ out, int nnodes) {
    __shared__ double shs[256], shq[256];
    const int c = threadIdx.x & 63;
    const int g = threadIdx.x >> 6;
    double s = 0.0, q = 0.0;
    for (int r = blockIdx.x * 4 + g; r < nnodes; r += gridDim.x * 4) {
        float v = out[(size_t)r * D + c];
        s += v;
        q += (double)v * v;
    }
    shs[threadIdx.x] = s; shq[threadIdx.x] = q;
    __syncthreads();
    if (g == 0) {
        s = shs[c] + shs[c + 64] + shs[c + 128] + shs[c + 192];
        q = shq[c] + shq[c + 64] + shq[c + 128] + shq[c + 192];
        atomicAdd(&g_sums[c], s);
        atomicAdd(&g_sums[64 + c], q);
    }
}

__global__ void k_bnprep(const float* __restrict__ gamma,
                         const float* __restrict__ beta, int nnodes) {
    int c = threadIdx.x;
    if (c < 64) {
        double mean = g_sums[c] / nnodes;
        double var  = g_sums[64 + c] / nnodes - mean * mean;
        float scale = gamma[c] * rsqrtf((float)var + BN_EPS);
        g_bnsc[c] = scale;
        g_bnsh[c] = beta[c] - (float)mean * scale;
    }
}

__global__ void k_bnfinal(float* __restrict__ out, int nnodes) {
    int i = blockIdx.x * blockDim.x + threadIdx.x;
    int total = nnodes * 16;
    if (i >= total) return;
    int c4 = (i & 15) << 2;
    float4 v = ((float4*)out)[i];
    float4 sc = *(const float4*)(g_bnsc + c4);
    float4 sh = *(const float4*)(g_bnsh + c4);
    v.x = fmaxf(0.f, v.x * sc.x + sh.x);
    v.y = fmaxf(0.f, v.y * sc.y + sh.y);
    v.z = fmaxf(0.f, v.z * sc.z + sh.z);
    v.w = fmaxf(0.f, v.w * sc.w + sh.w);
    ((float4*)out)[i] = v;
}

// ============================================================================
extern "C" void kernel_launch(void* const* d_in, const int* in_sizes, int n_in,
                              void* d_out, int out_size)
{
    const float* x    = (const float*)d_in[0];
    const int*   ei   = (const int*)  d_in[1];
    const float* Wlin = (const float*)d_in[2];
    const float* blin = (const float*)d_in[3];
    const float* pw   = (const float*)d_in[4];
    const float* Wgat = (const float*)d_in[5];
    const float* attS = (const float*)d_in[6];
    const float* attD = (const float*)d_in[7];
    // d_in[8] = gat_bias: cancels under batch-stat BatchNorm.
    const float* gamma = (const float*)d_in[9];
    const float* beta  = (const float*)d_in[10];
    float* out = (float*)d_out;

    int n = in_sizes[0] / D;     // 50000
    int e = in_sizes[1] / 2;     // 800000
    const int* srcA = ei;
    const int* dstA = ei + e;

    static int inited = 0;
    if (!inited) {
        cudaFuncSetAttribute(k_ulinear, cudaFuncAttributeMaxDynamicSharedMemorySize, KA_SMEM);
        cudaFuncSetAttribute(k_hgemm,   cudaFuncAttributeMaxDynamicSharedMemorySize, KB_SMEM);
        inited = 1;
    }

    int nch = (n + 511) / 512;
    int nblk = (n + 63) / 64;

    k_prep_vec<<<1, 256>>>(Wgat, attS, attD);                                // 0
    k_zero<<<200, 256>>>(n);                                                 // 1
    k_ulinear<<<nblk, 256, KA_SMEM>>>(x, Wlin, blin, pw, dstA, n, e);        // 2
    k_hgemm<<<nblk, 256, KB_SMEM>>>(Wgat, n);                                // 3 (profiled)
    k_scanA<<<nch, 512>>>(n);                                                // 4
    k_scanB<<<1, 256>>>(nch);                                                // 5
    k_scanC<<<(n + 255) / 256, 256>>>(n, e);                                 // 6
    k_edgeW<<<(e + n + 255) / 256, 256>>>(srcA, dstA, n, e);                 // 7
    k_gather<<<(n * 32 + 255) / 256, 256>>>(out, n);                         // 8
    k_bnstats<<<200, 256>>>(out, n);                                         // 9
    k_bnprep<<<1, 64>>>(gamma, beta, n);                                     // 10
    k_bnfinal<<<(n * 16 + 255) / 256, 256>>>(out, n);                        // 11
}

// round 9
// speedup vs baseline: 1.2092x; 1.1632x over previous
#include <cuda_runtime.h>
#include <cuda_fp16.h>
#include <mma.h>
#include <cstdint>
#include <cstddef>

using namespace nvcuda;

#define D   64
#define H   4
#define NEG 0.2f
#define BN_EPS 1e-5f

#define NMAX 50000
#define EMAX 800000

// ---------------- scratch (static device globals; no allocation) ----------------
__device__ __half  g_uh[(size_t)NMAX * 64];     // [N][64] fp16 post-PReLU features
__device__ __half  g_zh[(size_t)NMAX * 256];    // [N][h*64+k] fp16 aggregated u
__device__ __half  g_wgT[64 * 256];             // B[j][h*64+k] = Wgat[(h*64+j)*64+k]
__device__ float  g_asrc[NMAX * H];
__device__ float  g_adst[NMAX * H];
__device__ float  g_wcsr[(size_t)EMAX * H];     // per-edge weights (CSR order)
__device__ float  g_wself[NMAX * H];
__device__ float  g_dnm[NMAX * H];              // softmax denominators (atomic)
__device__ float  g_cs[H * D];                  // W_gat_h^T att_src_h
__device__ float  g_cd[H * D];                  // W_gat_h^T att_dst_h
__device__ int    g_cnt[NMAX];
__device__ int    g_rowptr[NMAX + 1];
__device__ int    g_cursor[NMAX];
__device__ int    g_csrc[EMAX];
__device__ int    g_bsum[256];
__device__ double g_sums[128];                  // [0:64) sum, [64:128) sumsq
__device__ float  g_bnsc[64], g_bnsh[64];

// ---------------- fast exp: FMA polynomial (no MUFU) ----------------
__device__ __forceinline__ float fexp(float x) {
    x = fmaxf(x, -80.f);
    float y  = x * 1.44269504089f;
    float t  = y + 12582912.0f;
    int   ki = __float_as_int(t) - 0x4B400000;
    float r  = y - (t - 12582912.0f);
    float p  = 1.5403530e-4f;
    p = fmaf(p, r, 1.3333558e-3f);
    p = fmaf(p, r, 9.6181291e-3f);
    p = fmaf(p, r, 5.5504109e-2f);
    p = fmaf(p, r, 2.4022651e-1f);
    p = fmaf(p, r, 6.9314718e-1f);
    p = fmaf(p, r, 1.0f);
    return __int_as_float(__float_as_int(p) + (ki << 23));
}

__device__ __forceinline__ float lrelu(float v) { return (v >= 0.f) ? v : NEG * v; }

// ============================================================================
// prep: c_src/c_dst projection vectors + fp16 B matrix for gemm2
// ============================================================================
__global__ void k_prep_vec(const float* __restrict__ Wgat,
                           const float* __restrict__ attS,
                           const float* __restrict__ attD) {
    int tid = threadIdx.x;              // 256
    {
        int h = tid >> 6, k = tid & 63;
        float s = 0.f, d2 = 0.f;
        #pragma unroll 8
        for (int dd = 0; dd < 64; dd++) {
            float wv = Wgat[(h * 64 + dd) * 64 + k];
            s  += attS[h * 64 + dd] * wv;
            d2 += attD[h * 64 + dd] * wv;
        }
        g_cs[tid] = s;
        g_cd[tid] = d2;
    }
    // B[j][h*64+k] = Wgat[(h*64+j)*64+k]
    for (int i = tid; i < 64 * 256; i += 256) {
        int j = i >> 8, c = i & 255;
        int h = c >> 6, k = c & 63;
        g_wgT[j * 256 + c] = __float2half_rn(Wgat[(h * 64 + j) * 64 + k]);
    }
}

__global__ void k_zero(int n) {
    int gid = blockIdx.x * blockDim.x + threadIdx.x;
    int stride = gridDim.x * blockDim.x;
    for (int i = gid; i < n; i += stride) g_cnt[i] = 0;
    for (int i = gid; i < n * 4; i += stride) g_dnm[i] = 0.f;
    if (blockIdx.x == 0 && threadIdx.x < 128) g_sums[threadIdx.x] = 0.0;
}

// ============================================================================
// K_A: u = PReLU(x W_lin^T + b) -> g_uh (fp16);  a_src/a_dst dots;  histogram.
// ============================================================================
#define KA_FLOATS (4608 + 4608 + 2*68*4 + 2304)
#define KA_SMEM   (KA_FLOATS * 4)

__global__ __launch_bounds__(256) void k_ulinear(
    const float* __restrict__ x, const float* __restrict__ Wlin,
    const float* __restrict__ blin, const float* __restrict__ pw,
    const int* __restrict__ dstA, int nrows, int nedges)
{
    extern __shared__ float sm[];
    float*  sX  = sm;                        // [64][72] x tile; later aliased by sU
    float*  sU  = sm;                        // [col][row] u fp32 (alias of sX)
    float*  sW  = sm + 4608;                 // [64][72] Wlin^T
    float*  sC  = sm + 9216;                 // [4][68]
    float*  sC2 = sm + 9216 + 272;           // [4][68]
    __half* sUh = (__half*)(sm + 9760);      // [row][72] u fp16
    const int tid  = threadIdx.x;
    const int row0 = blockIdx.x * 64;

    // destination histogram (independent, overlaps)
    {
        int gid = blockIdx.x * 256 + tid;
        int stride = gridDim.x * 256;
        for (int i = gid; i < nedges; i += stride)
            atomicAdd(&g_cnt[dstA[i]], 1);
    }

    {
        int h = tid >> 6, k = tid & 63;
        sC [h * 68 + k] = g_cs[tid];
        sC2[h * 68 + k] = g_cd[tid];
    }
    for (int i = tid; i < 64 * 64; i += 256) {
        int r = i >> 6, k = i & 63;
        int gr = row0 + r;
        sX[k * 72 + r] = (gr < nrows) ? x[(size_t)gr * D + k] : 0.f;
    }
    for (int i = tid; i < 64 * 64; i += 256) {
        int j = i >> 6, k = i & 63;
        sW[k * 72 + j] = Wlin[i];
    }
    __syncthreads();

    float accv[4][4];
    {
        const int rg = (tid >> 4) << 2;
        const int cg = (tid & 15) << 2;
        #pragma unroll
        for (int a = 0; a < 4; a++)
            #pragma unroll
            for (int b = 0; b < 4; b++) accv[a][b] = 0.f;
        #pragma unroll 8
        for (int k = 0; k < 64; k++) {
            float4 a4 = *(const float4*)(sX + k * 72 + rg);
            float4 b4 = *(const float4*)(sW + k * 72 + cg);
            float av[4] = {a4.x, a4.y, a4.z, a4.w};
            float bv[4] = {b4.x, b4.y, b4.z, b4.w};
            #pragma unroll
            for (int ri = 0; ri < 4; ri++)
                #pragma unroll
                for (int cj = 0; cj < 4; cj++) accv[ri][cj] += av[ri] * bv[cj];
        }
    }
    __syncthreads();   // all reads of sX done; safe to alias with sU

    {
        const int rg = (tid >> 4) << 2;
        const int cg = (tid & 15) << 2;
        float4 bb = *(const float4*)(blin + cg);
        float4 pp = *(const float4*)(pw + cg);
        float bvb[4] = {bb.x, bb.y, bb.z, bb.w};
        float pvb[4] = {pp.x, pp.y, pp.z, pp.w};
        #pragma unroll
        for (int ri = 0; ri < 4; ri++)
            #pragma unroll
            for (int cj = 0; cj < 4; cj++) {
                float v = accv[ri][cj] + bvb[cj];
                v = (v >= 0.f) ? v : pvb[cj] * v;
                sU[(cg + cj) * 72 + rg + ri]  = v;
                sUh[(rg + ri) * 72 + cg + cj] = __float2half_rn(v);
            }
    }
    __syncthreads();

    // att dots from fp32 sU
    {
        const int r = tid >> 2, h = tid & 3;
        float sa = 0.f, da = 0.f;
        #pragma unroll 8
        for (int k = 0; k < 64; k++) {
            float uv = sU[k * 72 + r];
            sa += uv * sC [h * 68 + k];
            da += uv * sC2[h * 68 + k];
        }
        int gr = row0 + r;
        if (gr < nrows) {
            g_asrc[gr * 4 + h] = sa;
            g_adst[gr * 4 + h] = da;
        }
    }

    // coalesced fp16 u store
    for (int i = tid; i < 512; i += 256) {
        int r = i >> 3, q = i & 7;
        int gr = row0 + r;
        if (gr < nrows)
            *(uint4*)(g_uh + (size_t)gr * 64 + q * 8) =
                *(const uint4*)(sUh + r * 72 + q * 8);
    }
}

// ============================================================================
// scan
// ============================================================================
__global__ void k_scanA(int n) {
    __shared__ int sh[512];
    int i = blockIdx.x * 512 + threadIdx.x;
    int v = (i < n) ? g_cnt[i] : 0;
    sh[threadIdx.x] = v;
    __syncthreads();
    #pragma unroll
    for (int off = 1; off < 512; off <<= 1) {
        int t = (threadIdx.x >= off) ? sh[threadIdx.x - off] : 0;
        __syncthreads();
        sh[threadIdx.x] += t;
        __syncthreads();
    }
    if (i < n) g_rowptr[i] = sh[threadIdx.x] - v;
    if (threadIdx.x == 511) g_bsum[blockIdx.x] = sh[511];
}

__global__ void k_scanB(int nch) {
    __shared__ int sh[256];
    int v = (threadIdx.x < nch) ? g_bsum[threadIdx.x] : 0;
    sh[threadIdx.x] = v;
    __syncthreads();
    #pragma unroll
    for (int off = 1; off < 256; off <<= 1) {
        int t = (threadIdx.x >= off) ? sh[threadIdx.x - off] : 0;
        __syncthreads();
        sh[threadIdx.x] += t;
        __syncthreads();
    }
    if (threadIdx.x < nch) g_bsum[threadIdx.x] = sh[threadIdx.x] - v;
}

__global__ void k_scanC(int n, int e) {
    int i = blockIdx.x * blockDim.x + threadIdx.x;
    if (i < n) {
        int v = g_rowptr[i] + g_bsum[i >> 9];
        g_rowptr[i] = v;
        g_cursor[i] = v;
    }
    if (i == 0) g_rowptr[n] = e;
}

// ============================================================================
// K2: fused edge weights + CSR scatter
// ============================================================================
__global__ __launch_bounds__(256) void k_edgeW(const int* __restrict__ src,
                                               const int* __restrict__ dst,
                                               int n, int e)
{
    int i = blockIdx.x * 256 + threadIdx.x;
    if (i < e) {
        int s = src[i], d = dst[i];
        float4 a = ((const float4*)g_asrc)[s];
        float4 b = ((const float4*)g_adst)[d];
        float4 w = make_float4(fexp(lrelu(a.x + b.x)), fexp(lrelu(a.y + b.y)),
                               fexp(lrelu(a.z + b.z)), fexp(lrelu(a.w + b.w)));
        int pos = atomicAdd(&g_cursor[d], 1);
        g_csrc[pos] = s;
        ((float4*)g_wcsr)[pos] = w;
        float* dn = g_dnm + d * 4;
        atomicAdd(dn + 0, w.x);
        atomicAdd(dn + 1, w.y);
        atomicAdd(dn + 2, w.z);
        atomicAdd(dn + 3, w.w);
    } else if (i < e + n) {
        int v = i - e;
        float4 a = ((const float4*)g_asrc)[v];
        float4 b = ((const float4*)g_adst)[v];
        float4 w = make_float4(fexp(lrelu(a.x + b.x)), fexp(lrelu(a.y + b.y)),
                               fexp(lrelu(a.z + b.z)), fexp(lrelu(a.w + b.w)));
        ((float4*)g_wself)[v] = w;
        float* dn = g_dnm + v * 4;
        atomicAdd(dn + 0, w.x);
        atomicAdd(dn + 1, w.y);
        atomicAdd(dn + 2, w.z);
        atomicAdd(dn + 3, w.w);
    }
}

// ============================================================================
// K4: warp-per-node gather over u (fp16, 128B/edge). lane = dim pair.
//     z[n][h*64+2lane..] = (0.25/denom_h) * sum_e w_he * u[src]
// ============================================================================
__global__ __launch_bounds__(256) void k_gather(int n)
{
    int gw = (blockIdx.x * blockDim.x + threadIdx.x) >> 5;
    if (gw >= n) return;
    const int lane = threadIdx.x & 31;

    float4 ws = ((const float4*)g_wself)[gw];
    float2 u = __half22float2(((const __half2*)g_uh)[(size_t)gw * 32 + lane]);
    float2 A0 = make_float2(ws.x * u.x, ws.x * u.y);
    float2 A1 = make_float2(ws.y * u.x, ws.y * u.y);
    float2 A2 = make_float2(ws.z * u.x, ws.z * u.y);
    float2 A3 = make_float2(ws.w * u.x, ws.w * u.y);

    const int eb = g_rowptr[gw], ee = g_rowptr[gw + 1];
    #pragma unroll 4
    for (int e = eb; e < ee; e++) {
        int src  = g_csrc[e];
        float4 w = ((const float4*)g_wcsr)[e];
        float2 v = __half22float2(((const __half2*)g_uh)[(size_t)src * 32 + lane]);
        A0.x = fmaf(w.x, v.x, A0.x); A0.y = fmaf(w.x, v.y, A0.y);
        A1.x = fmaf(w.y, v.x, A1.x); A1.y = fmaf(w.y, v.y, A1.y);
        A2.x = fmaf(w.z, v.x, A2.x); A2.y = fmaf(w.z, v.y, A2.y);
        A3.x = fmaf(w.w, v.x, A3.x); A3.y = fmaf(w.w, v.y, A3.y);
    }

    float4 dn = ((const float4*)g_dnm)[gw];
    float i0 = 0.25f / dn.x, i1 = 0.25f / dn.y, i2 = 0.25f / dn.z, i3 = 0.25f / dn.w;
    __half2* z = (__half2*)(g_zh + (size_t)gw * 256);
    z[0 * 32 + lane] = __floats2half2_rn(A0.x * i0, A0.y * i0);
    z[1 * 32 + lane] = __floats2half2_rn(A1.x * i1, A1.y * i1);
    z[2 * 32 + lane] = __floats2half2_rn(A2.x * i2, A2.y * i2);
    z[3 * 32 + lane] = __floats2half2_rn(A3.x * i3, A3.y * i3);
}

// ============================================================================
// K5: out = z B^T via wmma fp16 (M=64, N=64, K=256), ldm=264 padding,
//     direct fp32 store_matrix_sync to out for full blocks.
// ============================================================================
#define KG_SMEM (2 * 64 * 264 * 2)   // two fp16 tiles [64][264]

__global__ __launch_bounds__(256) void k_gemm2(float* __restrict__ out, int nrows)
{
    extern __shared__ __half smh[];
    __half* sZh = smh;                 // [64][264]
    __half* sB  = smh + 64 * 264;      // [64][264]
    const int tid  = threadIdx.x;
    const int row0 = blockIdx.x * 64;
    const int rmax = nrows - row0;

    for (int i = tid; i < 64 * 32; i += 256) {
        int r = i >> 5, q = i & 31;
        uint4 v = make_uint4(0u, 0u, 0u, 0u);
        if (r < rmax) v = *(const uint4*)(g_zh + (size_t)(row0 + r) * 256 + q * 8);
        *(uint4*)(sZh + r * 264 + q * 8) = v;
    }
    for (int i = tid; i < 64 * 32; i += 256) {
        int r = i >> 5, q = i & 31;
        *(uint4*)(sB + r * 264 + q * 8) = *(const uint4*)(g_wgT + r * 256 + q * 8);
    }
    __syncthreads();

    const int wid = tid >> 5;
    const int mg  = wid >> 1;          // m tile 0..3
    const int ng  = (wid & 1) * 2;     // n tiles ng, ng+1

    wmma::fragment<wmma::accumulator, 16, 16, 16, float> acc[2];
    wmma::fill_fragment(acc[0], 0.0f);
    wmma::fill_fragment(acc[1], 0.0f);

    #pragma unroll
    for (int ks = 0; ks < 16; ks++) {
        wmma::fragment<wmma::matrix_a, 16, 16, 16, __half, wmma::row_major> af;
        wmma::load_matrix_sync(af, sZh + mg * 16 * 264 + ks * 16, 264);
        #pragma unroll
        for (int t = 0; t < 2; t++) {
            wmma::fragment<wmma::matrix_b, 16, 16, 16, __half, wmma::col_major> bf;
            wmma::load_matrix_sync(bf, sB + (ng + t) * 16 * 264 + ks * 16, 264);
            wmma::mma_sync(acc[t], af, bf, acc[t]);
        }
    }

    if (rmax >= 64) {
        #pragma unroll
        for (int t = 0; t < 2; t++)
            wmma::store_matrix_sync(out + (size_t)(row0 + mg * 16) * 64 + (ng + t) * 16,
                                    acc[t], 64, wmma::mem_row_major);
    } else {
        __syncthreads();   // uniform per block: safe
        float* stg = (float*)smh + wid * 320;   // 16 x 20
        const int lane = tid & 31;
        #pragma unroll
        for (int t = 0; t < 2; t++) {
            wmma::store_matrix_sync(stg, acc[t], 20, wmma::mem_row_major);
            __syncwarp();
            for (int j = lane; j < 256; j += 32) {
                int rr = j >> 4, cc = j & 15;
                int node = row0 + mg * 16 + rr;
                if (node < nrows)
                    out[(size_t)node * 64 + (ng + t) * 16 + cc] = stg[rr * 20 + cc];
            }
            __syncwarp();
        }
    }
}

// ============================================================================
// BatchNorm (batch stats; gat_bias cancels) + ReLU
// ============================================================================
__global__ void k_bnstats(const float* __restrict__ out, int nnodes) {
    __shared__ double shs[256], shq[256];
    const int c = threadIdx.x & 63;
    const int g = threadIdx.x >> 6;
    double s = 0.0, q = 0.0;
    for (int r = blockIdx.x * 4 + g; r < nnodes; r += gridDim.x * 4) {
        float v = out[(size_t)r * D + c];
        s += v;
        q += (double)v * v;
    }
    shs[threadIdx.x] = s; shq[threadIdx.x] = q;
    __syncthreads();
    if (g == 0) {
        s = shs[c] + shs[c + 64] + shs[c + 128] + shs[c + 192];
        q = shq[c] + shq[c + 64] + shq[c + 128] + shq[c + 192];
        atomicAdd(&g_sums[c], s);
        atomicAdd(&g_sums[64 + c], q);
    }
}

__global__ void k_bnprep(const float* __restrict__ gamma,
                         const float* __restrict__ beta, int nnodes) {
    int c = threadIdx.x;
    if (c < 64) {
        double mean = g_sums[c] / nnodes;
        double var  = g_sums[64 + c] / nnodes - mean * mean;
        float scale = gamma[c] * rsqrtf((float)var + BN_EPS);
        g_bnsc[c] = scale;
        g_bnsh[c] = beta[c] - (float)mean * scale;
    }
}

__global__ void k_bnfinal(float* __restrict__ out, int nnodes) {
    int i = blockIdx.x * blockDim.x + threadIdx.x;
    int total = nnodes * 16;
    if (i >= total) return;
    int c4 = (i & 15) << 2;
    float4 v = ((float4*)out)[i];
    float4 sc = *(const float4*)(g_bnsc + c4);
    float4 sh = *(const float4*)(g_bnsh + c4);
    v.x = fmaxf(0.f, v.x * sc.x + sh.x);
    v.y = fmaxf(0.f, v.y * sc.y + sh.y);
    v.z = fmaxf(0.f, v.z * sc.z + sh.z);
    v.w = fmaxf(0.f, v.w * sc.w + sh.w);
    ((float4*)out)[i] = v;
}

// ============================================================================
extern "C" void kernel_launch(void* const* d_in, const int* in_sizes, int n_in,
                              void* d_out, int out_size)
{
    const float* x    = (const float*)d_in[0];
    const int*   ei   = (const int*)  d_in[1];
    const float* Wlin = (const float*)d_in[2];
    const float* blin = (const float*)d_in[3];
    const float* pw   = (const float*)d_in[4];
    const float* Wgat = (const float*)d_in[5];
    const float* attS = (const float*)d_in[6];
    const float* attD = (const float*)d_in[7];
    // d_in[8] = gat_bias: cancels under batch-stat BatchNorm.
    const float* gamma = (const float*)d_in[9];
    const float* beta  = (const float*)d_in[10];
    float* out = (float*)d_out;

    int n = in_sizes[0] / D;     // 50000
    int e = in_sizes[1] / 2;     // 800000
    const int* srcA = ei;
    const int* dstA = ei + e;

    static int inited = 0;
    if (!inited) {
        cudaFuncSetAttribute(k_ulinear, cudaFuncAttributeMaxDynamicSharedMemorySize, KA_SMEM);
        cudaFuncSetAttribute(k_gemm2,   cudaFuncAttributeMaxDynamicSharedMemorySize, KG_SMEM);
        inited = 1;
    }

    int nch = (n + 511) / 512;
    int nblk = (n + 63) / 64;

    k_zero<<<200, 256>>>(n);                                                 // 0
    k_prep_vec<<<1, 256>>>(Wgat, attS, attD);                                // 1
    k_ulinear<<<nblk, 256, KA_SMEM>>>(x, Wlin, blin, pw, dstA, n, e);        // 2
    k_scanA<<<nch, 512>>>(n);                                                // 3 (profiled)
    k_scanB<<<1, 256>>>(nch);                                                // 4
    k_scanC<<<(n + 255) / 256, 256>>>(n, e);                                 // 5
    k_edgeW<<<(e + n + 255) / 256, 256>>>(srcA, dstA, n, e);                 // 6
    k_gather<<<(n * 32 + 255) / 256, 256>>>(n);                              // 7
    k_gemm2<<<nblk, 256, KG_SMEM>>>(out, n);                                 // 8
    k_bnstats<<<200, 256>>>(out, n);                                         // 9
    k_bnprep<<<1, 64>>>(gamma, beta, n);                                     // 10
    k_bnfinal<<<(n * 16 + 255) / 256, 256>>>(out, n);                        // 11
}